// round 5
// baseline (speedup 1.0000x reference)
#include <cuda_runtime.h>
#include <cuda_bf16.h>
#include <cstdint>
#include <math_constants.h>

// Problem shape (fixed per reference)
#define B_  32
#define S_  4096
#define H_  1024
#define CHUNKS 32             // s-chunks per batch (finer for tail smoothing)
#define SC  (S_ / CHUNKS)     // 128 rows per chunk
#define TR  8                 // rows per tile (one row per warp)
#define NT  (SC / TR)         // 16 tiles per chunk
#define NS  3                 // pipeline stages
#define TILE_BYTES (TR * H_ * 4)       // 32 KB
#define STAGE_FLOATS (TR * H_)

// SMEM layout (bytes)
#define SM_STAGES_OFF 0
#define SM_DEC_OFF    (NS * TILE_BYTES)              // 98304
#define SM_SCORE_OFF  (SM_DEC_OFF + H_ * 4)          // +4096
#define SM_MBAR_OFF   (SM_SCORE_OFF + 32)            // 8-byte aligned
#define SMEM_BYTES    (SM_MBAR_OFF + NS * 8 + 8)

// Scratch for cross-chunk combine (__device__ globals: allocation-free)
__device__ float g_m[B_ * CHUNKS];
__device__ float g_l[B_ * CHUNKS];
__device__ float g_ctx[(size_t)B_ * CHUNKS * H_];

__device__ __forceinline__ uint32_t smem_u32(const void* p) {
    uint32_t a;
    asm("{ .reg .u64 t; cvta.to.shared.u64 t, %1; cvt.u32.u64 %0, t; }"
        : "=r"(a) : "l"(p));
    return a;
}

__device__ __forceinline__ void mbar_init(uint32_t mbar, uint32_t cnt) {
    asm volatile("mbarrier.init.shared.b64 [%0], %1;" :: "r"(mbar), "r"(cnt) : "memory");
}
__device__ __forceinline__ void mbar_expect_tx(uint32_t mbar, uint32_t bytes) {
    asm volatile("mbarrier.arrive.expect_tx.shared.b64 _, [%0], %1;"
                 :: "r"(mbar), "r"(bytes) : "memory");
}
__device__ __forceinline__ void mbar_wait(uint32_t mbar, uint32_t parity) {
    uint32_t done;
    asm volatile(
        "{\n\t"
        ".reg .pred p;\n\t"
        "mbarrier.try_wait.parity.acquire.cta.shared::cta.b64 p, [%1], %2;\n\t"
        "selp.b32 %0, 1, 0, p;\n\t"
        "}" : "=r"(done) : "r"(mbar), "r"(parity) : "memory");
    if (!done) {
        asm volatile(
            "{\n\t"
            ".reg .pred P1;\n\t"
            "WAIT_LOOP_%=:\n\t"
            "mbarrier.try_wait.parity.acquire.cta.shared::cta.b64 P1, [%0], %1, 0x989680;\n\t"
            "@P1 bra.uni WAIT_DONE_%=;\n\t"
            "bra.uni WAIT_LOOP_%=;\n\t"
            "WAIT_DONE_%=:\n\t"
            "}" :: "r"(mbar), "r"(parity) : "memory");
    }
}
__device__ __forceinline__ void bulk_g2s(uint32_t dst, const void* src,
                                         uint32_t bytes, uint32_t mbar) {
    asm volatile(
        "cp.async.bulk.shared::cluster.global.mbarrier::complete_tx::bytes "
        "[%0], [%1], %2, [%3];"
        :: "r"(dst), "l"(src), "r"(bytes), "r"(mbar) : "memory");
}

// ---------------------------------------------------------------------------
// Pass 1: single streaming pass over encoder_outputs.
//   - raw scores -> attn region of d_out
//   - per-chunk (m, l, partial context) -> scratch
// ---------------------------------------------------------------------------
__global__ void __launch_bounds__(256)
attn_pass1(const float* __restrict__ dec,
           const float* __restrict__ enc,
           float* __restrict__ attn_scores)   // points at d_out + B_*H_
{
    extern __shared__ __align__(16) char smem[];
    float* s_stage = (float*)(smem + SM_STAGES_OFF);
    float* s_dec   = (float*)(smem + SM_DEC_OFF);
    float* s_score = (float*)(smem + SM_SCORE_OFF);
    uint32_t smbase = smem_u32(smem);
    uint32_t mbar0  = smbase + SM_MBAR_OFF;

    const int b     = blockIdx.y;
    const int chunk = blockIdx.x;
    const int tid   = threadIdx.x;
    const int w     = tid >> 5;
    const int lid   = tid & 31;

    const float* encB = enc + ((size_t)b * S_ + (size_t)chunk * SC) * H_;

    // init barriers + stage dec into smem
    if (tid == 0) {
        #pragma unroll
        for (int s = 0; s < NS; s++) mbar_init(mbar0 + 8u * s, 1);
    }
    ((float4*)s_dec)[tid] = ((const float4*)(dec + (size_t)b * H_))[tid];
    __syncthreads();

    if (tid == 0) {
        #pragma unroll
        for (int s = 0; s < NS; s++) {
            mbar_expect_tx(mbar0 + 8u * s, TILE_BYTES);
            bulk_g2s(smbase + SM_STAGES_OFF + s * TILE_BYTES,
                     encB + (size_t)s * TR * H_, TILE_BYTES, mbar0 + 8u * s);
        }
    }

    // decoder slice in registers: dreg[k] = dec4[k*32 + lid]
    float4 dreg[8];
    #pragma unroll
    for (int k = 0; k < 8; k++) dreg[k] = ((float4*)s_dec)[k * 32 + lid];

    float4 acc = make_float4(0.f, 0.f, 0.f, 0.f);
    float m = -CUDART_INF_F;
    float l = 0.f;

    for (int t = 0; t < NT; t++) {
        const int st = t % NS;
        const uint32_t ph = (uint32_t)((t / NS) & 1);
        const uint32_t mbar = mbar0 + 8u * st;
        mbar_wait(mbar, ph);

        float4* e = (float4*)(s_stage + st * STAGE_FLOATS);   // [TR][256] float4

        // ---- score for row w (warp-parallel over h) ----
        float4* er = e + w * 256;
        float p = 0.f;
        #pragma unroll
        for (int k = 0; k < 8; k++) {
            float4 v = er[k * 32 + lid];
            p = fmaf(dreg[k].x, v.x, p);
            p = fmaf(dreg[k].y, v.y, p);
            p = fmaf(dreg[k].z, v.z, p);
            p = fmaf(dreg[k].w, v.w, p);
        }
        #pragma unroll
        for (int off = 16; off > 0; off >>= 1)
            p += __shfl_xor_sync(0xFFFFFFFFu, p, off);
        if (lid == 0) {
            s_score[w] = p;
            attn_scores[(size_t)b * S_ + chunk * SC + t * TR + w] = p;
        }
        __syncthreads();

        // ---- online softmax update (all threads, identical values) ----
        float sc0[TR];
        float tm = m;
        #pragma unroll
        for (int r = 0; r < TR; r++) { sc0[r] = s_score[r]; tm = fmaxf(tm, sc0[r]); }
        if (tm > m) {
            float scale = __expf(m - tm);
            m = tm;
            l *= scale;
            acc.x *= scale; acc.y *= scale; acc.z *= scale; acc.w *= scale;
        }
        // weights: lanes 0..7 compute one exp each, broadcast via shfl
        float myw = (lid < TR) ? __expf(sc0[lid] - m) : 0.f;

        // ---- context accumulation: warp w owns cols [w*128, w*128+128) ----
        float4* ecol = e + w * 32 + lid;   // stride 256 float4 per row
        #pragma unroll
        for (int r = 0; r < TR; r++) {
            float wgt = __shfl_sync(0xFFFFFFFFu, myw, r);
            l += wgt;
            float4 v = ecol[r * 256];
            acc.x = fmaf(wgt, v.x, acc.x);
            acc.y = fmaf(wgt, v.y, acc.y);
            acc.z = fmaf(wgt, v.z, acc.z);
            acc.w = fmaf(wgt, v.w, acc.w);
        }
        __syncthreads();   // everyone done reading stage st

        if (tid == 0 && (t + NS) < NT) {
            mbar_expect_tx(mbar, TILE_BYTES);
            bulk_g2s(smbase + SM_STAGES_OFF + st * TILE_BYTES,
                     encB + (size_t)(t + NS) * TR * H_, TILE_BYTES, mbar);
        }
    }

    // epilogue: per-chunk partials
    const int cid = b * CHUNKS + chunk;
    ((float4*)(g_ctx + (size_t)cid * H_))[w * 32 + lid] = acc;
    if (tid == 0) { g_m[cid] = m; g_l[cid] = l; }
}

// ---------------------------------------------------------------------------
// Pass 2: per-batch combine of chunk partials + attn normalization.
// grid = (B_, 5): y==0 -> context reduce; y=1..4 -> normalize 1024 attn floats.
// Each block redundantly recomputes (M, L) from the tiny per-chunk arrays.
// ---------------------------------------------------------------------------
__global__ void __launch_bounds__(256)
attn_combine(float* __restrict__ ctx_out,      // d_out
             float* __restrict__ attn_out)     // d_out + B_*H_
{
    const int b    = blockIdx.x;
    const int part = blockIdx.y;
    const int tid  = threadIdx.x;

    float M = -CUDART_INF_F;
    #pragma unroll
    for (int c = 0; c < CHUNKS; c++) M = fmaxf(M, g_m[b * CHUNKS + c]);
    float L = 0.f;
    #pragma unroll
    for (int c = 0; c < CHUNKS; c++)
        L += g_l[b * CHUNKS + c] * __expf(g_m[b * CHUNKS + c] - M);
    const float invL = 1.0f / L;

    if (part == 0) {
        // context: 1024 floats = 256 float4, one per thread
        float4 s = make_float4(0.f, 0.f, 0.f, 0.f);
        #pragma unroll
        for (int c = 0; c < CHUNKS; c++) {
            float ef = __expf(g_m[b * CHUNKS + c] - M);
            float4 v = ((const float4*)(g_ctx + (size_t)(b * CHUNKS + c) * H_))[tid];
            s.x = fmaf(ef, v.x, s.x);
            s.y = fmaf(ef, v.y, s.y);
            s.z = fmaf(ef, v.z, s.z);
            s.w = fmaf(ef, v.w, s.w);
        }
        s.x *= invL; s.y *= invL; s.z *= invL; s.w *= invL;
        ((float4*)(ctx_out + (size_t)b * H_))[tid] = s;
    } else {
        // attn: normalize 1024 raw scores in place (256 float4, 1 per thread)
        float4* a4 = (float4*)(attn_out + (size_t)b * S_ + (size_t)(part - 1) * 1024);
        float4 x = a4[tid];
        x.x = __expf(x.x - M) * invL;
        x.y = __expf(x.y - M) * invL;
        x.z = __expf(x.z - M) * invL;
        x.w = __expf(x.w - M) * invL;
        a4[tid] = x;
    }
}

extern "C" void kernel_launch(void* const* d_in, const int* in_sizes, int n_in,
                              void* d_out, int out_size) {
    const float* dec = (const float*)d_in[0];   // (32, 1024)
    const float* enc = (const float*)d_in[1];   // (32, 4096, 1024)
    float* out = (float*)d_out;                 // [context (32*1024) | attn (32*4096)]
    float* ctx_out  = out;
    float* attn_out = out + (size_t)B_ * H_;

    cudaFuncSetAttribute(attn_pass1, cudaFuncAttributeMaxDynamicSharedMemorySize,
                         SMEM_BYTES);

    dim3 grid1(CHUNKS, B_);
    attn_pass1<<<grid1, 256, SMEM_BYTES>>>(dec, enc, attn_out);
    dim3 grid2(B_, 5);
    attn_combine<<<grid2, 256>>>(ctx_out, attn_out);
}

// round 7
// speedup vs baseline: 1.0986x; 1.0986x over previous
#include <cuda_runtime.h>
#include <cuda_bf16.h>
#include <cstdint>
#include <math_constants.h>

// Problem shape (fixed per reference)
#define B_  32
#define S_  4096
#define H_  1024
#define CHUNKS 16             // s-chunks per batch
#define SC  (S_ / CHUNKS)     // 256 rows per chunk
#define TR  8                 // rows per tile (one row per warp)
#define NT  (SC / TR)         // 32 tiles per chunk
#define NS  3                 // pipeline stages
#define TILE_BYTES (TR * H_ * 4)       // 32 KB
#define STAGE_FLOATS (TR * H_)

// SMEM layout (bytes)
#define SM_STAGES_OFF 0
#define SM_DEC_OFF    (NS * TILE_BYTES)              // 98304
#define SM_ML_OFF     (SM_DEC_OFF + H_ * 4)          // m[8], l[8]
#define SM_MBAR_OFF   (SM_ML_OFF + 64 + 8)
#define SMEM_BYTES    (SM_MBAR_OFF + NS * 8 + 8)

// Scratch for cross-chunk combine (__device__ globals: allocation-free)
__device__ float g_m[B_ * CHUNKS];
__device__ float g_l[B_ * CHUNKS];
__device__ float g_ctx[(size_t)B_ * CHUNKS * H_];

__device__ __forceinline__ uint32_t smem_u32(const void* p) {
    uint32_t a;
    asm("{ .reg .u64 t; cvta.to.shared.u64 t, %1; cvt.u32.u64 %0, t; }"
        : "=r"(a) : "l"(p));
    return a;
}

__device__ __forceinline__ void mbar_init(uint32_t mbar, uint32_t cnt) {
    asm volatile("mbarrier.init.shared.b64 [%0], %1;" :: "r"(mbar), "r"(cnt) : "memory");
}
__device__ __forceinline__ void mbar_expect_tx(uint32_t mbar, uint32_t bytes) {
    asm volatile("mbarrier.arrive.expect_tx.shared.b64 _, [%0], %1;"
                 :: "r"(mbar), "r"(bytes) : "memory");
}
__device__ __forceinline__ void mbar_wait(uint32_t mbar, uint32_t parity) {
    uint32_t done;
    asm volatile(
        "{\n\t"
        ".reg .pred p;\n\t"
        "mbarrier.try_wait.parity.acquire.cta.shared::cta.b64 p, [%1], %2;\n\t"
        "selp.b32 %0, 1, 0, p;\n\t"
        "}" : "=r"(done) : "r"(mbar), "r"(parity) : "memory");
    if (!done) {
        asm volatile(
            "{\n\t"
            ".reg .pred P1;\n\t"
            "WAIT_LOOP_%=:\n\t"
            "mbarrier.try_wait.parity.acquire.cta.shared::cta.b64 P1, [%0], %1, 0x989680;\n\t"
            "@P1 bra.uni WAIT_DONE_%=;\n\t"
            "bra.uni WAIT_LOOP_%=;\n\t"
            "WAIT_DONE_%=:\n\t"
            "}" :: "r"(mbar), "r"(parity) : "memory");
    }
}
__device__ __forceinline__ void bulk_g2s(uint32_t dst, const void* src,
                                         uint32_t bytes, uint32_t mbar) {
    asm volatile(
        "cp.async.bulk.shared::cluster.global.mbarrier::complete_tx::bytes "
        "[%0], [%1], %2, [%3];"
        :: "r"(dst), "l"(src), "r"(bytes), "r"(mbar) : "memory");
}

// ---------------------------------------------------------------------------
// Pass 1: single streaming pass over encoder_outputs.
// Per-warp independent online softmax: each warp owns one row per tile,
// keeps the row in registers (read SMEM once), accumulates its own
// (m, l, acc) and merges across the 8 warps once at chunk end.
// ---------------------------------------------------------------------------
__global__ void __launch_bounds__(256, 2)
attn_pass1(const float* __restrict__ dec,
           const float* __restrict__ enc,
           float* __restrict__ attn_scores)   // points at d_out + B_*H_
{
    extern __shared__ __align__(16) char smem[];
    float* s_stage = (float*)(smem + SM_STAGES_OFF);
    float* s_dec   = (float*)(smem + SM_DEC_OFF);
    float* s_m     = (float*)(smem + SM_ML_OFF);
    float* s_l     = s_m + TR;
    uint32_t smbase = smem_u32(smem);
    uint32_t mbar0  = smbase + SM_MBAR_OFF;

    const int b     = blockIdx.y;
    const int chunk = blockIdx.x;
    const int tid   = threadIdx.x;
    const int w     = tid >> 5;
    const int lid   = tid & 31;

    const float* encB = enc + ((size_t)b * S_ + (size_t)chunk * SC) * H_;

    if (tid == 0) {
        #pragma unroll
        for (int s = 0; s < NS; s++) mbar_init(mbar0 + 8u * s, 1);
    }
    ((float4*)s_dec)[tid] = ((const float4*)(dec + (size_t)b * H_))[tid];
    __syncthreads();

    if (tid == 0) {
        #pragma unroll
        for (int s = 0; s < NS; s++) {
            mbar_expect_tx(mbar0 + 8u * s, TILE_BYTES);
            bulk_g2s(smbase + SM_STAGES_OFF + s * TILE_BYTES,
                     encB + (size_t)s * TR * H_, TILE_BYTES, mbar0 + 8u * s);
        }
    }

    // decoder slice in registers: dreg[k] = dec4[k*32 + lid]
    float4 dreg[8];
    #pragma unroll
    for (int k = 0; k < 8; k++) dreg[k] = ((float4*)s_dec)[k * 32 + lid];

    float4 acc[8];
    #pragma unroll
    for (int k = 0; k < 8; k++) acc[k] = make_float4(0.f, 0.f, 0.f, 0.f);
    float m = -CUDART_INF_F;
    float l = 0.f;

    for (int t = 0; t < NT; t++) {
        const int st = t % NS;
        const uint32_t ph = (uint32_t)((t / NS) & 1);
        const uint32_t mbar = mbar0 + 8u * st;
        mbar_wait(mbar, ph);

        // warp w's row of this tile, into registers (single SMEM read)
        float4* er = (float4*)(s_stage + st * STAGE_FLOATS) + w * 256;
        float4 v[8];
        #pragma unroll
        for (int k = 0; k < 8; k++) v[k] = er[k * 32 + lid];

        // score (consumes all v loads -> safe to free the stage after)
        float p = 0.f;
        #pragma unroll
        for (int k = 0; k < 8; k++) {
            p = fmaf(dreg[k].x, v[k].x, p);
            p = fmaf(dreg[k].y, v[k].y, p);
            p = fmaf(dreg[k].z, v[k].z, p);
            p = fmaf(dreg[k].w, v[k].w, p);
        }
        #pragma unroll
        for (int off = 16; off > 0; off >>= 1)
            p += __shfl_xor_sync(0xFFFFFFFFu, p, off);

        __syncthreads();   // all warps' loads done -> stage reusable
        if (tid == 0 && (t + NS) < NT) {
            mbar_expect_tx(mbar, TILE_BYTES);
            bulk_g2s(smbase + SM_STAGES_OFF + st * TILE_BYTES,
                     encB + (size_t)(t + NS) * TR * H_, TILE_BYTES, mbar);
        }

        if (lid == 0)
            attn_scores[(size_t)b * S_ + chunk * SC + t * TR + w] = p;

        // per-warp online softmax update (overlaps with TMA refill)
        if (p > m) {
            float scale = __expf(m - p);
            m = p;
            l *= scale;
            #pragma unroll
            for (int k = 0; k < 8; k++) {
                acc[k].x *= scale; acc[k].y *= scale;
                acc[k].z *= scale; acc[k].w *= scale;
            }
        }
        float wgt = __expf(p - m);
        l += wgt;
        #pragma unroll
        for (int k = 0; k < 8; k++) {
            acc[k].x = fmaf(wgt, v[k].x, acc[k].x);
            acc[k].y = fmaf(wgt, v[k].y, acc[k].y);
            acc[k].z = fmaf(wgt, v[k].z, acc[k].z);
            acc[k].w = fmaf(wgt, v[k].w, acc[k].w);
        }
    }

    // ---- merge the 8 per-warp (m, l, acc) triples ----
    if (lid == 0) { s_m[w] = m; s_l[w] = l; }
    __syncthreads();

    float M = -CUDART_INF_F;
    #pragma unroll
    for (int r = 0; r < TR; r++) M = fmaxf(M, s_m[r]);
    float L = 0.f;
    #pragma unroll
    for (int r = 0; r < TR; r++) L += s_l[r] * __expf(s_m[r] - M);
    float myscale = __expf(m - M);   // uniform within warp

    // scaled per-warp acc -> stage scratch (stage 0 region, 32 KB)
    float4* dst = (float4*)s_stage + w * 256;
    #pragma unroll
    for (int k = 0; k < 8; k++) {
        float4 a = acc[k];
        a.x *= myscale; a.y *= myscale; a.z *= myscale; a.w *= myscale;
        dst[k * 32 + lid] = a;
    }
    __syncthreads();

    // sum 8 distributed vectors -> one context partial (256 float4)
    float4* sb = (float4*)s_stage;
    float4 s = make_float4(0.f, 0.f, 0.f, 0.f);
    #pragma unroll
    for (int r = 0; r < TR; r++) {
        float4 x = sb[r * 256 + tid];
        s.x += x.x; s.y += x.y; s.z += x.z; s.w += x.w;
    }
    const int cid = b * CHUNKS + chunk;
    ((float4*)(g_ctx + (size_t)cid * H_))[tid] = s;
    if (tid == 0) { g_m[cid] = M; g_l[cid] = L; }
}

// ---------------------------------------------------------------------------
// Pass 2: per-batch combine of chunk partials + attn normalization.
// grid = (B_, 5): y==0 -> context reduce; y=1..4 -> normalize 1024 attn floats.
// ---------------------------------------------------------------------------
__global__ void __launch_bounds__(256)
attn_combine(float* __restrict__ ctx_out,      // d_out
             float* __restrict__ attn_out)     // d_out + B_*H_
{
    const int b    = blockIdx.x;
    const int part = blockIdx.y;
    const int tid  = threadIdx.x;

    float M = -CUDART_INF_F;
    #pragma unroll
    for (int c = 0; c < CHUNKS; c++) M = fmaxf(M, g_m[b * CHUNKS + c]);
    float L = 0.f;
    #pragma unroll
    for (int c = 0; c < CHUNKS; c++)
        L += g_l[b * CHUNKS + c] * __expf(g_m[b * CHUNKS + c] - M);
    const float invL = 1.0f / L;

    if (part == 0) {
        float4 s = make_float4(0.f, 0.f, 0.f, 0.f);
        #pragma unroll
        for (int c = 0; c < CHUNKS; c++) {
            float ef = __expf(g_m[b * CHUNKS + c] - M);
            float4 v = ((const float4*)(g_ctx + (size_t)(b * CHUNKS + c) * H_))[tid];
            s.x = fmaf(ef, v.x, s.x);
            s.y = fmaf(ef, v.y, s.y);
            s.z = fmaf(ef, v.z, s.z);
            s.w = fmaf(ef, v.w, s.w);
        }
        s.x *= invL; s.y *= invL; s.z *= invL; s.w *= invL;
        ((float4*)(ctx_out + (size_t)b * H_))[tid] = s;
    } else {
        float4* a4 = (float4*)(attn_out + (size_t)b * S_ + (size_t)(part - 1) * 1024);
        float4 x = a4[tid];
        x.x = __expf(x.x - M) * invL;
        x.y = __expf(x.y - M) * invL;
        x.z = __expf(x.z - M) * invL;
        x.w = __expf(x.w - M) * invL;
        a4[tid] = x;
    }
}

extern "C" void kernel_launch(void* const* d_in, const int* in_sizes, int n_in,
                              void* d_out, int out_size) {
    const float* dec = (const float*)d_in[0];   // (32, 1024)
    const float* enc = (const float*)d_in[1];   // (32, 4096, 1024)
    float* out = (float*)d_out;                 // [context (32*1024) | attn (32*4096)]
    float* ctx_out  = out;
    float* attn_out = out + (size_t)B_ * H_;

    cudaFuncSetAttribute(attn_pass1, cudaFuncAttributeMaxDynamicSharedMemorySize,
                         SMEM_BYTES);

    dim3 grid1(CHUNKS, B_);
    attn_pass1<<<grid1, 256, SMEM_BYTES>>>(dec, enc, attn_out);
    dim3 grid2(B_, 5);
    attn_combine<<<grid2, 256>>>(ctx_out, attn_out);
}

// round 8
// speedup vs baseline: 1.1038x; 1.0047x over previous
#include <cuda_runtime.h>
#include <cuda_bf16.h>
#include <cstdint>
#include <math_constants.h>

// Problem shape (fixed per reference)
#define B_  32
#define S_  4096
#define H_  1024
#define CHUNKS 16             // s-chunks per batch
#define SC  (S_ / CHUNKS)     // 256 rows per chunk
#define TR  8                 // rows per tile (one row per warp)
#define NT  (SC / TR)         // 32 tiles per chunk
#define NS  3                 // pipeline stages
#define TILE_BYTES (TR * H_ * 4)       // 32 KB
#define STAGE_FLOATS (TR * H_)

// SMEM layout (bytes)
#define SM_STAGES_OFF 0
#define SM_DEC_OFF    (NS * TILE_BYTES)              // 98304
#define SM_ML_OFF     (SM_DEC_OFF + H_ * 4)          // m[8], l[8]
#define SM_FLAG_OFF   (SM_ML_OFF + 64)               // int flag
#define SM_MBAR_OFF   (SM_FLAG_OFF + 8)
#define SMEM_BYTES    (SM_MBAR_OFF + NS * 8 + 8)

// Scratch (__device__ globals: allocation-free)
__device__ float g_m[B_ * CHUNKS];
__device__ float g_l[B_ * CHUNKS];
__device__ float g_ctx[(size_t)B_ * CHUNKS * H_];
__device__ int   g_cnt[B_];   // zero-initialized; reset in-kernel each launch

__device__ __forceinline__ uint32_t smem_u32(const void* p) {
    uint32_t a;
    asm("{ .reg .u64 t; cvta.to.shared.u64 t, %1; cvt.u32.u64 %0, t; }"
        : "=r"(a) : "l"(p));
    return a;
}

__device__ __forceinline__ void mbar_init(uint32_t mbar, uint32_t cnt) {
    asm volatile("mbarrier.init.shared.b64 [%0], %1;" :: "r"(mbar), "r"(cnt) : "memory");
}
__device__ __forceinline__ void mbar_expect_tx(uint32_t mbar, uint32_t bytes) {
    asm volatile("mbarrier.arrive.expect_tx.shared.b64 _, [%0], %1;"
                 :: "r"(mbar), "r"(bytes) : "memory");
}
__device__ __forceinline__ void mbar_wait(uint32_t mbar, uint32_t parity) {
    uint32_t done;
    asm volatile(
        "{\n\t"
        ".reg .pred p;\n\t"
        "mbarrier.try_wait.parity.acquire.cta.shared::cta.b64 p, [%1], %2;\n\t"
        "selp.b32 %0, 1, 0, p;\n\t"
        "}" : "=r"(done) : "r"(mbar), "r"(parity) : "memory");
    if (!done) {
        asm volatile(
            "{\n\t"
            ".reg .pred P1;\n\t"
            "WAIT_LOOP_%=:\n\t"
            "mbarrier.try_wait.parity.acquire.cta.shared::cta.b64 P1, [%0], %1, 0x989680;\n\t"
            "@P1 bra.uni WAIT_DONE_%=;\n\t"
            "bra.uni WAIT_LOOP_%=;\n\t"
            "WAIT_DONE_%=:\n\t"
            "}" :: "r"(mbar), "r"(parity) : "memory");
    }
}
__device__ __forceinline__ void bulk_g2s(uint32_t dst, const void* src,
                                         uint32_t bytes, uint32_t mbar) {
    asm volatile(
        "cp.async.bulk.shared::cluster.global.mbarrier::complete_tx::bytes "
        "[%0], [%1], %2, [%3];"
        :: "r"(dst), "l"(src), "r"(bytes), "r"(mbar) : "memory");
}

// ---------------------------------------------------------------------------
// Single fused kernel: streaming online-softmax pass + last-CTA-per-batch
// combine (threadfence-reduction pattern).
// ---------------------------------------------------------------------------
__global__ void __launch_bounds__(256, 2)
attn_fused(const float* __restrict__ dec,
           const float* __restrict__ enc,
           float* __restrict__ ctx_out,       // d_out
           float* __restrict__ attn_out)      // d_out + B_*H_
{
    extern __shared__ __align__(16) char smem[];
    float* s_stage = (float*)(smem + SM_STAGES_OFF);
    float* s_dec   = (float*)(smem + SM_DEC_OFF);
    float* s_m     = (float*)(smem + SM_ML_OFF);
    float* s_l     = s_m + TR;
    int*   s_last  = (int*)(smem + SM_FLAG_OFF);
    uint32_t smbase = smem_u32(smem);
    uint32_t mbar0  = smbase + SM_MBAR_OFF;

    const int b     = blockIdx.y;
    const int chunk = blockIdx.x;
    const int tid   = threadIdx.x;
    const int w     = tid >> 5;
    const int lid   = tid & 31;

    const float* encB = enc + ((size_t)b * S_ + (size_t)chunk * SC) * H_;

    if (tid == 0) {
        #pragma unroll
        for (int s = 0; s < NS; s++) mbar_init(mbar0 + 8u * s, 1);
    }
    ((float4*)s_dec)[tid] = ((const float4*)(dec + (size_t)b * H_))[tid];
    __syncthreads();

    if (tid == 0) {
        #pragma unroll
        for (int s = 0; s < NS; s++) {
            mbar_expect_tx(mbar0 + 8u * s, TILE_BYTES);
            bulk_g2s(smbase + SM_STAGES_OFF + s * TILE_BYTES,
                     encB + (size_t)s * TR * H_, TILE_BYTES, mbar0 + 8u * s);
        }
    }

    // decoder slice in registers
    float4 dreg[8];
    #pragma unroll
    for (int k = 0; k < 8; k++) dreg[k] = ((float4*)s_dec)[k * 32 + lid];

    float4 acc[8];
    #pragma unroll
    for (int k = 0; k < 8; k++) acc[k] = make_float4(0.f, 0.f, 0.f, 0.f);
    float m = -CUDART_INF_F;
    float l = 0.f;

    for (int t = 0; t < NT; t++) {
        const int st = t % NS;
        const uint32_t ph = (uint32_t)((t / NS) & 1);
        const uint32_t mbar = mbar0 + 8u * st;
        mbar_wait(mbar, ph);

        // warp w's row of this tile, into registers (single SMEM read)
        float4* er = (float4*)(s_stage + st * STAGE_FLOATS) + w * 256;
        float4 v[8];
        #pragma unroll
        for (int k = 0; k < 8; k++) v[k] = er[k * 32 + lid];

        float p = 0.f;
        #pragma unroll
        for (int k = 0; k < 8; k++) {
            p = fmaf(dreg[k].x, v[k].x, p);
            p = fmaf(dreg[k].y, v[k].y, p);
            p = fmaf(dreg[k].z, v[k].z, p);
            p = fmaf(dreg[k].w, v[k].w, p);
        }
        #pragma unroll
        for (int off = 16; off > 0; off >>= 1)
            p += __shfl_xor_sync(0xFFFFFFFFu, p, off);

        __syncthreads();   // all warps' loads done -> stage reusable
        if (tid == 0 && (t + NS) < NT) {
            mbar_expect_tx(mbar, TILE_BYTES);
            bulk_g2s(smbase + SM_STAGES_OFF + st * TILE_BYTES,
                     encB + (size_t)(t + NS) * TR * H_, TILE_BYTES, mbar);
        }

        if (lid == 0)
            attn_out[(size_t)b * S_ + chunk * SC + t * TR + w] = p;   // raw score

        // per-warp online softmax update (overlaps with TMA refill)
        if (p > m) {
            float scale = __expf(m - p);
            m = p;
            l *= scale;
            #pragma unroll
            for (int k = 0; k < 8; k++) {
                acc[k].x *= scale; acc[k].y *= scale;
                acc[k].z *= scale; acc[k].w *= scale;
            }
        }
        float wgt = __expf(p - m);
        l += wgt;
        #pragma unroll
        for (int k = 0; k < 8; k++) {
            acc[k].x = fmaf(wgt, v[k].x, acc[k].x);
            acc[k].y = fmaf(wgt, v[k].y, acc[k].y);
            acc[k].z = fmaf(wgt, v[k].z, acc[k].z);
            acc[k].w = fmaf(wgt, v[k].w, acc[k].w);
        }
    }

    // ---- merge the 8 per-warp (m, l, acc) triples ----
    if (lid == 0) { s_m[w] = m; s_l[w] = l; }
    __syncthreads();

    float Mc = -CUDART_INF_F;
    #pragma unroll
    for (int r = 0; r < TR; r++) Mc = fmaxf(Mc, s_m[r]);
    float Lc = 0.f;
    #pragma unroll
    for (int r = 0; r < TR; r++) Lc += s_l[r] * __expf(s_m[r] - Mc);
    float myscale = __expf(m - Mc);   // uniform within warp

    float4* dst = (float4*)s_stage + w * 256;
    #pragma unroll
    for (int k = 0; k < 8; k++) {
        float4 a = acc[k];
        a.x *= myscale; a.y *= myscale; a.z *= myscale; a.w *= myscale;
        dst[k * 32 + lid] = a;
    }
    __syncthreads();

    float4* sb = (float4*)s_stage;
    float4 s = make_float4(0.f, 0.f, 0.f, 0.f);
    #pragma unroll
    for (int r = 0; r < TR; r++) {
        float4 x = sb[r * 256 + tid];
        s.x += x.x; s.y += x.y; s.z += x.z; s.w += x.w;
    }
    const int cid = b * CHUNKS + chunk;
    ((float4*)(g_ctx + (size_t)cid * H_))[tid] = s;
    if (tid == 0) { g_m[cid] = Mc; g_l[cid] = Lc; }

    // ---- last CTA of this batch performs the combine ----
    __threadfence();   // release partials + raw scores
    if (tid == 0) {
        int old = atomicAdd(&g_cnt[b], 1);
        *s_last = (old == CHUNKS - 1);
    }
    __syncthreads();
    if (!*s_last) return;

    __threadfence();   // acquire all CTAs' partials/scores
    if (tid == 0) g_cnt[b] = 0;   // reset for next graph replay

    float M = -CUDART_INF_F;
    #pragma unroll
    for (int c = 0; c < CHUNKS; c++) M = fmaxf(M, g_m[b * CHUNKS + c]);
    float L = 0.f;
    #pragma unroll
    for (int c = 0; c < CHUNKS; c++)
        L += g_l[b * CHUNKS + c] * __expf(g_m[b * CHUNKS + c] - M);
    const float invL = 1.0f / L;

    // context: 1024 floats = 256 float4, one per thread
    float4 cs = make_float4(0.f, 0.f, 0.f, 0.f);
    #pragma unroll
    for (int c = 0; c < CHUNKS; c++) {
        float ef = __expf(g_m[b * CHUNKS + c] - M);
        float4 v = ((const float4*)(g_ctx + (size_t)(b * CHUNKS + c) * H_))[tid];
        cs.x = fmaf(ef, v.x, cs.x);
        cs.y = fmaf(ef, v.y, cs.y);
        cs.z = fmaf(ef, v.z, cs.z);
        cs.w = fmaf(ef, v.w, cs.w);
    }
    cs.x *= invL; cs.y *= invL; cs.z *= invL; cs.w *= invL;
    ((float4*)(ctx_out + (size_t)b * H_))[tid] = cs;

    // attn: normalize this batch's 4096 raw scores (1024 float4, 4/thread)
    float4* a4 = (float4*)(attn_out + (size_t)b * S_);
    #pragma unroll
    for (int i = 0; i < 4; i++) {
        float4 x = a4[i * 256 + tid];
        x.x = __expf(x.x - M) * invL;
        x.y = __expf(x.y - M) * invL;
        x.z = __expf(x.z - M) * invL;
        x.w = __expf(x.w - M) * invL;
        a4[i * 256 + tid] = x;
    }
}

extern "C" void kernel_launch(void* const* d_in, const int* in_sizes, int n_in,
                              void* d_out, int out_size) {
    const float* dec = (const float*)d_in[0];   // (32, 1024)
    const float* enc = (const float*)d_in[1];   // (32, 4096, 1024)
    float* out = (float*)d_out;                 // [context (32*1024) | attn (32*4096)]
    float* ctx_out  = out;
    float* attn_out = out + (size_t)B_ * H_;

    cudaFuncSetAttribute(attn_fused, cudaFuncAttributeMaxDynamicSharedMemorySize,
                         SMEM_BYTES);

    dim3 grid(CHUNKS, B_);
    attn_fused<<<grid, 256, SMEM_BYTES>>>(dec, enc, ctx_out, attn_out);
}